// round 8
// baseline (speedup 1.0000x reference)
#include <cuda_runtime.h>
#include <math.h>

typedef unsigned long long ull;
struct __align__(16) ULL2 { ull x, y; };

#define B_     64
#define F_     4097
#define FCL_   65
#define FL_    64
#define OUT_S  262144
#define NFRB   32          // frames per block
#define NWARP  8
#define ACCLEN 2176        // (NFRB-1)*64 + 192

// ---------------- packed f32x2 helpers ----------------
__device__ __forceinline__ ull fma2_(ull a, ull b, ull c) {
    ull d; asm("fma.rn.f32x2 %0,%1,%2,%3;" : "=l"(d) : "l"(a), "l"(b), "l"(c)); return d;
}
__device__ __forceinline__ ull add2_(ull a, ull b) {
    ull d; asm("add.rn.f32x2 %0,%1,%2;" : "=l"(d) : "l"(a), "l"(b)); return d;
}
__device__ __forceinline__ ull mul2_(ull a, ull b) {
    ull d; asm("mul.rn.f32x2 %0,%1,%2;" : "=l"(d) : "l"(a), "l"(b)); return d;
}
__device__ __forceinline__ ull dup_(float x) {
    ull d; unsigned r = __float_as_uint(x);
    asm("mov.b64 %0,{%1,%1};" : "=l"(d) : "r"(r)); return d;
}
__device__ __forceinline__ ull pk_(float lo, float hi) {
    ull d; asm("mov.b64 %0,{%1,%2};" : "=l"(d) : "r"(__float_as_uint(lo)), "r"(__float_as_uint(hi))); return d;
}
__device__ __forceinline__ void unpk_(ull v, float& lo, float& hi) {
    unsigned a, b; asm("mov.b64 {%0,%1},%2;" : "=r"(a), "=r"(b) : "l"(v));
    lo = __uint_as_float(a); hi = __uint_as_float(b);
}

// ---------------- tables (L1-cached via __ldg; int mod-129 reduction) ----------------
__device__ float2 g_cosP[64 * 32];   // [k-1][l] = (cos(th*k*(l+1)), cos(th*k*(l+33)))
__device__ float  g_win[130];

// prep: build tables AND zero only the block-boundary strips of out
__global__ void prep_k(float4* __restrict__ out4) {
    const int i = blockIdx.x * blockDim.x + threadIdx.x;
    const float TH = 6.283185307179586477f / 129.0f;
    if (i < 64 * 32) {
        int k = (i >> 5) + 1, l = i & 31;
        int m1 = (k * (l + 1))  % 129;
        int m2 = (k * (l + 33)) % 129;
        g_cosP[i] = make_float2(cosf(TH * (float)m1), cosf(TH * (float)m2));
    }
    if (i < 130) g_win[i] = 0.5f - 0.5f * cosf(TH * (float)i);
    if (i < 64 * 128 * 32) {
        const int b  = i >> 12;
        const int r  = i & 4095;
        const int q  = r >> 5;
        const int j4 = r & 31;
        out4[b * 65536 + q * 512 + j4] = make_float4(0.f, 0.f, 0.f, 0.f);
    }
}

__device__ __forceinline__ float msig(float x) {
    float sg = 1.0f / (1.0f + __expf(-x));
    return 2.0f * __powf(sg, 2.302585092994046f) + 1e-7f;
}

// ---------------- wirb XOR swizzle (16B-chunk granularity) ----------------
__device__ __forceinline__ int swz_(int c) { return c ^ ((c >> 3) & 7); }
__device__ __forceinline__ ULL2 wld_(const float* wb, int c) {
    return *(const ULL2*)(wb + (swz_(c) << 2));
}
__device__ __forceinline__ void wst_(float* wb, int i, float v) {
    int c = i >> 2;
    wb[(swz_(c) << 2) | (i & 3)] = v;
}

// ---------------- dynamic smem layout (bytes) ----------------
// outb rows carry, in sequence: (a) staged s-pack + dup x, (b) zp spill, (c) conv output
#define WIR_OFF    0        // float[8][256]  = 8192 (swizzled; zero outside IR span)
#define OUTB_OFF   8192     // float[32][192] = 24576
#define S0_OFF     32768    // float[8][4]    = 128
#define SMEM_TOT   32896    // 32.1 KB -> 6 CTAs/SM

__global__ __launch_bounds__(256, 6) void fn_main(
        const float* __restrict__ coeff,   // (B, F, 65)
        const float* __restrict__ noise,   // (B, F, 64)
        float* __restrict__ out)           // (B, 262144)
{
    extern __shared__ __align__(16) char smdyn[];
    float* wirb  = (float*)(smdyn + WIR_OFF);     // [w][256] swizzled
    float* outb  = (float*)(smdyn + OUTB_OFF);    // [fi][192]
    float* s0arr = (float*)(smdyn + S0_OFF);      // [w][ff]

    const int tid = threadIdx.x;
    const int w   = tid >> 5;
    const int l   = tid & 31;
    const int q   = blockIdx.x;          // 0..127 (frames 0..4095; frame 4096 never contributes)
    const int b   = blockIdx.y;
    const int f0  = q * NFRB;

    // ---- zero wir buffers; stage inputs ----
    for (int i = tid; i < NWARP * 256; i += 256) wirb[i] = 0.f;
    // s-pack: warp w's frames ff=0..3 live in rows {w, w+8, w+16, w+24} floats [128..192):
    //   s_k (k=m+1) of frame ff at row (w + 8*(m>>4)), float 128 + 4*(m&15) + ff
    const size_t cbo = ((size_t)b * F_ + f0) * FCL_;
    for (int e = tid; e < NFRB * FCL_; e += 256) {
        const int fi = e / 65, k = e - fi * 65;
        const float v = msig(coeff[cbo + e]);
        const int ww = fi & 7, ff = fi >> 3;
        if (k == 0) s0arr[ww * 4 + ff] = v;
        else {
            const int m = k - 1;
            outb[(ww + 8 * (m >> 4)) * 192 + 128 + 4 * (m & 15) + ff] = v;
        }
    }
    // x staged PRE-DUPLICATED into row floats [0..128): (v,v) at [2t, 2t+1]
    const size_t nbo = ((size_t)b * F_ + f0) * FL_;
    for (int e = tid; e < NFRB * FL_; e += 256) {
        const int fi = e >> 6, t = e & 63;
        const float v = 2.f * noise[nbo + e] - 1.f;
        *(float2*)(outb + fi * 192 + 2 * t) = make_float2(v, v);
    }
    __syncthreads();

    const int t1 = l + 1, t2 = l + 33;
    float* wb = wirb + w * 256;

    // ---- cosine transform, 4 frames per warp jointly (packed f32x2) ----
    // zp[t] = (s0 + 2*sum_{k=1..64} s_k cos(2pi k t/129)) / 129 ; lane handles t1, t2
    ull ac0AB = 0, ac0CD = 0, ac1AB = 0, ac1CD = 0, ac2AB = 0, ac2CD = 0;
    const ULL2 s0p = *(const ULL2*)(s0arr + w * 4);
    #pragma unroll
    for (int blk = 0; blk < 4; blk++) {
        const float*  bp  = outb + (w + 8 * blk) * 192 + 128;
        const float2* cpb = g_cosP + blk * 16 * 32;
        #pragma unroll
        for (int r = 0; r < 16; r++) {
            const float2 ct = __ldg(&cpb[r * 32 + l]);
            const ULL2 sp = *(const ULL2*)(bp + 4 * r);   // broadcast LDS.128
            const ull c1d = dup_(ct.x), c2d = dup_(ct.y);
            ac1AB = fma2_(sp.x, c1d, ac1AB);  ac1CD = fma2_(sp.y, c1d, ac1CD);
            ac2AB = fma2_(sp.x, c2d, ac2AB);  ac2CD = fma2_(sp.y, c2d, ac2CD);
            ac0AB = add2_(ac0AB, sp.x);       ac0CD = add2_(ac0CD, sp.y);
        }
    }
    const ull TWO = dup_(2.0f), SCL = dup_(1.0f / 129.0f);
    float zp0s[4];
    {
        float z1[4], z2[4];
        ull r;
        r = mul2_(fma2_(ac0AB, TWO, s0p.x), SCL); unpk_(r, zp0s[0], zp0s[1]);
        r = mul2_(fma2_(ac0CD, TWO, s0p.y), SCL); unpk_(r, zp0s[2], zp0s[3]);
        r = mul2_(fma2_(ac1AB, TWO, s0p.x), SCL); unpk_(r, z1[0], z1[1]);
        r = mul2_(fma2_(ac1CD, TWO, s0p.y), SCL); unpk_(r, z1[2], z1[3]);
        r = mul2_(fma2_(ac2AB, TWO, s0p.x), SCL); unpk_(r, z2[0], z2[1]);
        r = mul2_(fma2_(ac2CD, TWO, s0p.y), SCL); unpk_(r, z2[2], z2[3]);
        __syncwarp();   // transform reads of row tails done before overwrite
        // spill zp1/zp2 through each frame's own row tail (same-lane store/reload)
        #pragma unroll
        for (int ff = 0; ff < 4; ff++) {
            float* zr = outb + (ff * 8 + w) * 192 + 128;
            zr[l]      = z1[ff];
            zr[32 + l] = z2[ff];
        }
    }

    // ---- per-frame: windowed IR build + 64x192 linear conv ----
    #pragma unroll
    for (int ff = 0; ff < 4; ff++) {
        const int fi = ff * NWARP + w;
        const float* zr = outb + fi * 192 + 128;
        const float zp1 = zr[l], zp2 = zr[32 + l];   // own-lane reload

        // wb[128 +/- t] = win * zp (zp even-symmetric)
        wst_(wb, 128 + t1, __ldg(&g_win[64 + t1]) * zp1);
        wst_(wb, 128 - t1, __ldg(&g_win[64 - t1]) * zp1);
        wst_(wb, 128 + t2, __ldg(&g_win[64 + t2]) * zp2);
        wst_(wb, 128 - t2, __ldg(&g_win[64 - t2]) * zp2);
        if (l == 0) wst_(wb, 128, __ldg(&g_win[64]) * zp0s[ff]);
        __syncwarp();

        // out[t] = sum_tau x[tau]*wb[64+t-tau], t = 8*ll + c (24 lanes x 8 outputs)
        const float* xs = outb + fi * 192;     // duplicated x pairs
        const int ll = (l < 24) ? l : 0;
        const int cb = 15 + 2 * ll;            // chunk of float index 60 + 8*ll
        ull acc0 = 0, acc1 = 0, acc2 = 0, acc3 = 0;
        ULL2 va = wld_(wb, cb);
        ULL2 vb = wld_(wb, cb + 1);
        ULL2 vc = wld_(wb, cb + 2);
        ull E0 = va.x, E1 = va.y, E2 = vb.x, E3 = vb.y, E4 = vc.x, E5 = vc.y;
        float f0v, f1v, f2v, f3v, f4v, f5v, f6v, f7v, f8v, f9v, f10v, f11v;
        unpk_(E0, f0v, f1v); unpk_(E1, f2v, f3v); unpk_(E2, f4v, f5v);
        unpk_(E3, f6v, f7v); unpk_(E4, f8v, f9v); unpk_(E5, f10v, f11v);
        ull O0 = pk_(f1v, f2v), O1 = pk_(f3v, f4v), O2 = pk_(f5v, f6v);
        ull O3 = pk_(f7v, f8v), O4 = pk_(f9v, f10v);
        float carry = f0v;

        #pragma unroll
        for (int g = 0; g < 16; g++) {
            const ULL2 xa = *(const ULL2*)(xs + 8 * g);        // (x0,x0),(x1,x1)
            const ULL2 xb2 = *(const ULL2*)(xs + 8 * g + 4);   // (x2,x2),(x3,x3)
            acc0 = fma2_(xa.x, E2, acc0); acc1 = fma2_(xa.x, E3, acc1);
            acc2 = fma2_(xa.x, E4, acc2); acc3 = fma2_(xa.x, E5, acc3);
            acc0 = fma2_(xa.y, O1, acc0); acc1 = fma2_(xa.y, O2, acc1);
            acc2 = fma2_(xa.y, O3, acc2); acc3 = fma2_(xa.y, O4, acc3);
            acc0 = fma2_(xb2.x, E1, acc0); acc1 = fma2_(xb2.x, E2, acc1);
            acc2 = fma2_(xb2.x, E3, acc2); acc3 = fma2_(xb2.x, E4, acc3);
            acc0 = fma2_(xb2.y, O0, acc0); acc1 = fma2_(xb2.y, O1, acc1);
            acc2 = fma2_(xb2.y, O2, acc2); acc3 = fma2_(xb2.y, O3, acc3);
            if (g < 15) {
                const ULL2 nw = wld_(wb, cb - 1 - g);
                float nf0, nf1, nf2, nf3;
                unpk_(nw.x, nf0, nf1); unpk_(nw.y, nf2, nf3);
                E5 = E3; E4 = E2; E3 = E1; E2 = E0; E1 = nw.y; E0 = nw.x;
                O4 = O2; O3 = O1; O2 = O0; O1 = pk_(nf3, carry); O0 = pk_(nf1, nf2);
                carry = nf0;
            }
        }
        __syncwarp();   // all lanes' x/zp reads done before the row is overwritten
        if (l < 24) {
            ULL2* op = (ULL2*)(outb + fi * 192 + 8 * l);
            op[0] = ULL2{acc0, acc1};
            op[1] = ULL2{acc2, acc3};
        }
        __syncwarp();   // wb/row settled before next frame
    }

    __syncthreads();

    // ---- overlap-add: interior exclusively owned, boundaries via atomics ----
    const size_t rowb = (size_t)b * OUT_S;
    const int gb = f0 * FL_;
    for (int p = tid; p < ACCLEN; p += 256) {
        const int P = gb + p;
        if (P >= OUT_S) continue;
        const int fhi = p >> 6;
        const int t0  = p & 63;
        float v = 0.f;
        if (fhi < NFRB)                 v += outb[fhi * 192 + t0];
        if (fhi >= 1 && fhi - 1 < NFRB) v += outb[(fhi - 1) * 192 + t0 + 64];
        if (fhi >= 2 && fhi - 2 < NFRB) v += outb[(fhi - 2) * 192 + t0 + 128];
        if (p >= 128 && p < 2048) out[rowb + P] = v;
        else                      atomicAdd(&out[rowb + P], v);
    }
}

extern "C" void kernel_launch(void* const* d_in, const int* in_sizes, int n_in,
                              void* d_out, int out_size) {
    const float* coeff = (const float*)d_in[0];
    const float* noise = (const float*)d_in[1];
    float* out = (float*)d_out;

    cudaFuncSetAttribute(fn_main, cudaFuncAttributeMaxDynamicSharedMemorySize, SMEM_TOT);
    prep_k<<<1024, 256>>>((float4*)out);
    dim3 grid(128, B_);
    fn_main<<<grid, 256, SMEM_TOT>>>(coeff, noise, out);
}

// round 9
// speedup vs baseline: 1.3068x; 1.3068x over previous
#include <cuda_runtime.h>
#include <math.h>

typedef unsigned long long ull;
struct __align__(16) ULL2 { ull x, y; };

#define B_     64
#define F_     4097
#define FCL_   65
#define FL_    64
#define OUT_S  262144
#define NFRB   32          // frames per block
#define NWARP  8
#define ACCLEN 2176        // (NFRB-1)*64 + 192

// ---------------- packed f32x2 helpers ----------------
__device__ __forceinline__ ull fma2_(ull a, ull b, ull c) {
    ull d; asm("fma.rn.f32x2 %0,%1,%2,%3;" : "=l"(d) : "l"(a), "l"(b), "l"(c)); return d;
}
__device__ __forceinline__ ull add2_(ull a, ull b) {
    ull d; asm("add.rn.f32x2 %0,%1,%2;" : "=l"(d) : "l"(a), "l"(b)); return d;
}
__device__ __forceinline__ ull mul2_(ull a, ull b) {
    ull d; asm("mul.rn.f32x2 %0,%1,%2;" : "=l"(d) : "l"(a), "l"(b)); return d;
}
__device__ __forceinline__ ull dup_(float x) {
    ull d; unsigned r = __float_as_uint(x);
    asm("mov.b64 %0,{%1,%1};" : "=l"(d) : "r"(r)); return d;
}
__device__ __forceinline__ ull pk_(float lo, float hi) {
    ull d; asm("mov.b64 %0,{%1,%2};" : "=l"(d) : "r"(__float_as_uint(lo)), "r"(__float_as_uint(hi))); return d;
}
__device__ __forceinline__ void unpk_(ull v, float& lo, float& hi) {
    unsigned a, b; asm("mov.b64 {%0,%1},%2;" : "=r"(a), "=r"(b) : "l"(v));
    lo = __uint_as_float(a); hi = __uint_as_float(b);
}

// ---------------- tables (L1-cached via __ldg; int mod-129 reduction) ----------------
__device__ float2 g_cosP[64 * 32];   // [k-1][l] = (cos(th*k*(l+1)), cos(th*k*(l+33)))
__device__ float  g_win[130];

// prep: build tables AND zero only the block-boundary strips of out
__global__ void prep_k(float4* __restrict__ out4) {
    const int i = blockIdx.x * blockDim.x + threadIdx.x;
    const float TH = 6.283185307179586477f / 129.0f;
    if (i < 64 * 32) {
        int k = (i >> 5) + 1, l = i & 31;
        int m1 = (k * (l + 1))  % 129;
        int m2 = (k * (l + 33)) % 129;
        g_cosP[i] = make_float2(cosf(TH * (float)m1), cosf(TH * (float)m2));
    }
    if (i < 130) g_win[i] = 0.5f - 0.5f * cosf(TH * (float)i);
    if (i < 64 * 128 * 32) {
        const int b  = i >> 12;
        const int r  = i & 4095;
        const int q  = r >> 5;
        const int j4 = r & 31;
        out4[b * 65536 + q * 512 + j4] = make_float4(0.f, 0.f, 0.f, 0.f);
    }
}

__device__ __forceinline__ float msig(float x) {
    float sg = 1.0f / (1.0f + __expf(-x));
    return 2.0f * __powf(sg, 2.302585092994046f) + 1e-7f;
}

// ---------------- wirb XOR swizzle (16B-chunk granularity) ----------------
__device__ __forceinline__ int swz_(int c) { return c ^ ((c >> 3) & 7); }
__device__ __forceinline__ ULL2 wld_(const float* wb, int c) {
    return *(const ULL2*)(wb + (swz_(c) << 2));
}
__device__ __forceinline__ void wst_(float* wb, int i, float v) {
    int c = i >> 2;
    wb[(swz_(c) << 2) | (i & 3)] = v;
}

// ---------------- dynamic smem layout (bytes) ----------------
#define SINTJ_OFF  0        // float[8][65][4] = 8320
#define WIR_OFF    8320     // float[8][256]   = 8192 (swizzled; zero outside IR span)
#define OUTB_OFF   16512    // float[32][192]  = 24576 (dup x staged in [fi][0..128) pre-conv)
#define SMEM_TOT   41088    // 40.1 KB -> 5 CTAs/SM

__global__ __launch_bounds__(256, 5) void fn_main(
        const float* __restrict__ coeff,   // (B, F, 65)
        const float* __restrict__ noise,   // (B, F, 64)
        float* __restrict__ out)           // (B, 262144)
{
    extern __shared__ __align__(16) char smdyn[];
    float* sIntJ = (float*)(smdyn + SINTJ_OFF);   // [w][k][ff]
    float* wirb  = (float*)(smdyn + WIR_OFF);     // [w][256] swizzled
    float* outb  = (float*)(smdyn + OUTB_OFF);    // [fi][192]

    const int tid = threadIdx.x;
    const int w   = tid >> 5;
    const int l   = tid & 31;
    const int q   = blockIdx.x;          // 0..127 (frames 0..4095; frame 4096 never contributes)
    const int b   = blockIdx.y;
    const int f0  = q * NFRB;

    // ---- stage inputs, zero wir buffers ----
    for (int i = tid; i < NWARP * 256; i += 256) wirb[i] = 0.f;
    const size_t cbo = ((size_t)b * F_ + f0) * FCL_;
    for (int e = tid; e < NFRB * FCL_; e += 256) {
        int fi = e / 65, k = e - fi * 65;
        sIntJ[(((fi & 7) * 65) + k) * 4 + (fi >> 3)] = msig(coeff[cbo + e]);
    }
    // x staged PRE-DUPLICATED into outb row floats [0..128): (v,v) at [2t, 2t+1]
    const size_t nbo = ((size_t)b * F_ + f0) * FL_;
    for (int e = tid; e < NFRB * FL_; e += 256) {
        int fi = e >> 6, t = e & 63;
        const float v = 2.f * noise[nbo + e] - 1.f;
        *(float2*)(outb + fi * 192 + 2 * t) = make_float2(v, v);
    }
    __syncthreads();

    const int t1 = l + 1, t2 = l + 33;
    float* wb = wirb + w * 256;

    // ---- cosine transform, 4 frames per warp jointly (packed f32x2) ----
    // zp[t] = (s0 + 2*sum_{k=1..64} s_k cos(2pi k t/129)) / 129 ; lane handles t1, t2
    const float* sw = sIntJ + w * 65 * 4;
    ull ac0AB = 0, ac0CD = 0, ac1AB = 0, ac1CD = 0, ac2AB = 0, ac2CD = 0;
    const ULL2 s0p = *(const ULL2*)sw;
    #pragma unroll 4
    for (int k = 1; k <= 64; k++) {
        const float2 ct = __ldg(&g_cosP[(k - 1) * 32 + l]);
        const ULL2 sp = *(const ULL2*)(sw + k * 4);   // broadcast LDS.128
        const ull c1d = dup_(ct.x), c2d = dup_(ct.y);
        ac1AB = fma2_(sp.x, c1d, ac1AB);  ac1CD = fma2_(sp.y, c1d, ac1CD);
        ac2AB = fma2_(sp.x, c2d, ac2AB);  ac2CD = fma2_(sp.y, c2d, ac2CD);
        ac0AB = add2_(ac0AB, sp.x);       ac0CD = add2_(ac0CD, sp.y);
    }
    const ull TWO = dup_(2.0f), SCL = dup_(1.0f / 129.0f);
    float zp0s[4], zp1s[4], zp2s[4];
    {
        ull r;
        r = mul2_(fma2_(ac0AB, TWO, s0p.x), SCL); unpk_(r, zp0s[0], zp0s[1]);
        r = mul2_(fma2_(ac0CD, TWO, s0p.y), SCL); unpk_(r, zp0s[2], zp0s[3]);
        r = mul2_(fma2_(ac1AB, TWO, s0p.x), SCL); unpk_(r, zp1s[0], zp1s[1]);
        r = mul2_(fma2_(ac1CD, TWO, s0p.y), SCL); unpk_(r, zp1s[2], zp1s[3]);
        r = mul2_(fma2_(ac2AB, TWO, s0p.x), SCL); unpk_(r, zp2s[0], zp2s[1]);
        r = mul2_(fma2_(ac2CD, TWO, s0p.y), SCL); unpk_(r, zp2s[2], zp2s[3]);
    }

    // ---- per-frame: windowed IR build + 64x192 linear conv ----
    #pragma unroll
    for (int ff = 0; ff < 4; ff++) {
        const int fi = ff * NWARP + w;

        // wb[128 +/- t] = win * zp (zp even-symmetric); win via L1
        wst_(wb, 128 + t1, __ldg(&g_win[64 + t1]) * zp1s[ff]);
        wst_(wb, 128 - t1, __ldg(&g_win[64 - t1]) * zp1s[ff]);
        wst_(wb, 128 + t2, __ldg(&g_win[64 + t2]) * zp2s[ff]);
        wst_(wb, 128 - t2, __ldg(&g_win[64 - t2]) * zp2s[ff]);
        if (l == 0) wst_(wb, 128, __ldg(&g_win[64]) * zp0s[ff]);
        __syncwarp();

        // out[t] = sum_tau x[tau]*wb[64+t-tau], t = 8*ll + c (24 lanes x 8 outputs)
        const float* xs = outb + fi * 192;     // duplicated x pairs
        const int ll = (l < 24) ? l : 0;
        const int cb = 15 + 2 * ll;            // chunk of float index 60 + 8*ll
        ull acc0 = 0, acc1 = 0, acc2 = 0, acc3 = 0;
        ULL2 va = wld_(wb, cb);
        ULL2 vb = wld_(wb, cb + 1);
        ULL2 vc = wld_(wb, cb + 2);
        ull E0 = va.x, E1 = va.y, E2 = vb.x, E3 = vb.y, E4 = vc.x, E5 = vc.y;
        float f0v, f1v, f2v, f3v, f4v, f5v, f6v, f7v, f8v, f9v, f10v, f11v;
        unpk_(E0, f0v, f1v); unpk_(E1, f2v, f3v); unpk_(E2, f4v, f5v);
        unpk_(E3, f6v, f7v); unpk_(E4, f8v, f9v); unpk_(E5, f10v, f11v);
        ull O0 = pk_(f1v, f2v), O1 = pk_(f3v, f4v), O2 = pk_(f5v, f6v);
        ull O3 = pk_(f7v, f8v), O4 = pk_(f9v, f10v);
        float carry = f0v;

        #pragma unroll
        for (int g = 0; g < 16; g++) {
            const ULL2 xa  = *(const ULL2*)(xs + 8 * g);       // (x0,x0),(x1,x1)
            const ULL2 xb2 = *(const ULL2*)(xs + 8 * g + 4);   // (x2,x2),(x3,x3)
            acc0 = fma2_(xa.x, E2, acc0); acc1 = fma2_(xa.x, E3, acc1);
            acc2 = fma2_(xa.x, E4, acc2); acc3 = fma2_(xa.x, E5, acc3);
            acc0 = fma2_(xa.y, O1, acc0); acc1 = fma2_(xa.y, O2, acc1);
            acc2 = fma2_(xa.y, O3, acc2); acc3 = fma2_(xa.y, O4, acc3);
            acc0 = fma2_(xb2.x, E1, acc0); acc1 = fma2_(xb2.x, E2, acc1);
            acc2 = fma2_(xb2.x, E3, acc2); acc3 = fma2_(xb2.x, E4, acc3);
            acc0 = fma2_(xb2.y, O0, acc0); acc1 = fma2_(xb2.y, O1, acc1);
            acc2 = fma2_(xb2.y, O2, acc2); acc3 = fma2_(xb2.y, O3, acc3);
            if (g < 15) {
                const ULL2 nw = wld_(wb, cb - 1 - g);
                float nf0, nf1, nf2, nf3;
                unpk_(nw.x, nf0, nf1); unpk_(nw.y, nf2, nf3);
                E5 = E3; E4 = E2; E3 = E1; E2 = E0; E1 = nw.y; E0 = nw.x;
                O4 = O2; O3 = O1; O2 = O0; O1 = pk_(nf3, carry); O0 = pk_(nf1, nf2);
                carry = nf0;
            }
        }
        __syncwarp();   // all lanes' x reads done before the row is overwritten
        if (l < 24) {
            ULL2* op = (ULL2*)(outb + fi * 192 + 8 * l);
            op[0] = ULL2{acc0, acc1};
            op[1] = ULL2{acc2, acc3};
        }
        __syncwarp();   // wb/row settled before next frame
    }

    __syncthreads();

    // ---- overlap-add: interior exclusively owned, boundaries via atomics ----
    const size_t rowb = (size_t)b * OUT_S;
    const int gb = f0 * FL_;
    for (int p = tid; p < ACCLEN; p += 256) {
        const int P = gb + p;
        if (P >= OUT_S) continue;
        const int fhi = p >> 6;
        const int t0  = p & 63;
        float v = 0.f;
        if (fhi < NFRB)                 v += outb[fhi * 192 + t0];
        if (fhi >= 1 && fhi - 1 < NFRB) v += outb[(fhi - 1) * 192 + t0 + 64];
        if (fhi >= 2 && fhi - 2 < NFRB) v += outb[(fhi - 2) * 192 + t0 + 128];
        if (p >= 128 && p < 2048) out[rowb + P] = v;
        else                      atomicAdd(&out[rowb + P], v);
    }
}

extern "C" void kernel_launch(void* const* d_in, const int* in_sizes, int n_in,
                              void* d_out, int out_size) {
    const float* coeff = (const float*)d_in[0];
    const float* noise = (const float*)d_in[1];
    float* out = (float*)d_out;

    cudaFuncSetAttribute(fn_main, cudaFuncAttributeMaxDynamicSharedMemorySize, SMEM_TOT);
    prep_k<<<1024, 256>>>((float4*)out);
    dim3 grid(128, B_);
    fn_main<<<grid, 256, SMEM_TOT>>>(coeff, noise, out);
}

// round 10
// speedup vs baseline: 1.4281x; 1.0928x over previous
#include <cuda_runtime.h>
#include <math.h>

typedef unsigned long long ull;
struct __align__(16) ULL2 { ull x, y; };

#define B_     64
#define F_     4097
#define FCL_   65
#define FL_    64
#define OUT_S  262144
#define NFRB   32          // frames per block
#define NWARP  8
#define ACCLEN 2176        // (NFRB-1)*64 + 192

// ---------------- packed f32x2 helpers ----------------
__device__ __forceinline__ ull fma2_(ull a, ull b, ull c) {
    ull d; asm("fma.rn.f32x2 %0,%1,%2,%3;" : "=l"(d) : "l"(a), "l"(b), "l"(c)); return d;
}
__device__ __forceinline__ ull add2_(ull a, ull b) {
    ull d; asm("add.rn.f32x2 %0,%1,%2;" : "=l"(d) : "l"(a), "l"(b)); return d;
}
__device__ __forceinline__ ull mul2_(ull a, ull b) {
    ull d; asm("mul.rn.f32x2 %0,%1,%2;" : "=l"(d) : "l"(a), "l"(b)); return d;
}
__device__ __forceinline__ ull dup_(float x) {
    ull d; unsigned r = __float_as_uint(x);
    asm("mov.b64 %0,{%1,%1};" : "=l"(d) : "r"(r)); return d;
}
__device__ __forceinline__ void unpk_(ull v, float& lo, float& hi) {
    unsigned a, b; asm("mov.b64 {%0,%1},%2;" : "=r"(a), "=r"(b) : "l"(v));
    lo = __uint_as_float(a); hi = __uint_as_float(b);
}

// ---------------- tables (L1-cached via __ldg; int mod-129 reduction) ----------------
__device__ float2 g_cosP[64 * 32];   // [k-1][l] = (cos(th*k*(l+1)), cos(th*k*(l+33)))
__device__ float  g_win[130];

// prep: build tables AND zero only the block-boundary strips of out
__global__ void prep_k(float4* __restrict__ out4) {
    const int i = blockIdx.x * blockDim.x + threadIdx.x;
    const float TH = 6.283185307179586477f / 129.0f;
    if (i < 64 * 32) {
        int k = (i >> 5) + 1, l = i & 31;
        int m1 = (k * (l + 1))  % 129;
        int m2 = (k * (l + 33)) % 129;
        g_cosP[i] = make_float2(cosf(TH * (float)m1), cosf(TH * (float)m2));
    }
    if (i < 130) g_win[i] = 0.5f - 0.5f * cosf(TH * (float)i);
    if (i < 64 * 128 * 32) {
        const int b  = i >> 12;
        const int r  = i & 4095;
        const int q  = r >> 5;
        const int j4 = r & 31;
        out4[b * 65536 + q * 512 + j4] = make_float4(0.f, 0.f, 0.f, 0.f);
    }
}

__device__ __forceinline__ float msig(float x) {
    float sg = 1.0f / (1.0f + __expf(-x));
    return 2.0f * __powf(sg, 2.302585092994046f) + 1e-7f;
}

// ---------------- wirb XOR swizzle (16B-chunk granularity) ----------------
__device__ __forceinline__ int swz_(int c) { return c ^ ((c >> 3) & 7); }
__device__ __forceinline__ ULL2 wld_(const float* wb, int c) {
    return *(const ULL2*)(wb + (swz_(c) << 2));
}
__device__ __forceinline__ void wst_(float* wb, int i, float v) {
    int c = i >> 2;
    wb[(swz_(c) << 2) | (i & 3)] = v;
}

// ---------------- dynamic smem layout (bytes) ----------------
#define SINTJ_OFF  0        // float[8][65][4] = 8320
#define WIR_OFF    8320     // float[8][256]   = 8192 (swizzled; zero outside IR span)
#define OUTB_OFF   16512    // float[32][192]  = 24576 (x staged in [fi][0..64) pre-conv)
#define SMEM_TOT   41088    // 40.1 KB -> 5 CTAs/SM

__global__ __launch_bounds__(256, 5) void fn_main(
        const float* __restrict__ coeff,   // (B, F, 65)
        const float* __restrict__ noise,   // (B, F, 64)
        float* __restrict__ out)           // (B, 262144)
{
    extern __shared__ __align__(16) char smdyn[];
    float* sIntJ = (float*)(smdyn + SINTJ_OFF);   // [w][k][ff]
    float* wirb  = (float*)(smdyn + WIR_OFF);     // [w][256] swizzled
    float* outb  = (float*)(smdyn + OUTB_OFF);    // [fi][192]

    const int tid = threadIdx.x;
    const int w   = tid >> 5;
    const int l   = tid & 31;
    const int q   = blockIdx.x;          // 0..127 (frames 0..4095; frame 4096 never contributes)
    const int b   = blockIdx.y;
    const int f0  = q * NFRB;

    // ---- stage inputs, zero wir buffers ----
    for (int i = tid; i < NWARP * 256; i += 256) wirb[i] = 0.f;
    const size_t cbo = ((size_t)b * F_ + f0) * FCL_;
    for (int e = tid; e < NFRB * FCL_; e += 256) {
        int fi = e / 65, k = e - fi * 65;
        sIntJ[(((fi & 7) * 65) + k) * 4 + (fi >> 3)] = msig(coeff[cbo + e]);
    }
    // x staged plain into the first 64 floats of each outb row
    const size_t nbo = ((size_t)b * F_ + f0) * FL_;
    for (int e = tid; e < NFRB * FL_; e += 256) {
        int fi = e >> 6, t = e & 63;
        outb[fi * 192 + t] = 2.f * noise[nbo + e] - 1.f;
    }
    __syncthreads();

    const int t1 = l + 1, t2 = l + 33;
    float* wb = wirb + w * 256;

    // ---- cosine transform, 4 frames per warp jointly (packed f32x2) ----
    // zp[t] = (s0 + 2*sum_{k=1..64} s_k cos(2pi k t/129)) / 129 ; lane handles t1, t2
    const float* sw = sIntJ + w * 65 * 4;
    ull ac0AB = 0, ac0CD = 0, ac1AB = 0, ac1CD = 0, ac2AB = 0, ac2CD = 0;
    const ULL2 s0p = *(const ULL2*)sw;
    #pragma unroll 4
    for (int k = 1; k <= 64; k++) {
        const float2 ct = __ldg(&g_cosP[(k - 1) * 32 + l]);
        const ULL2 sp = *(const ULL2*)(sw + k * 4);   // broadcast LDS.128
        const ull c1d = dup_(ct.x), c2d = dup_(ct.y);
        ac1AB = fma2_(sp.x, c1d, ac1AB);  ac1CD = fma2_(sp.y, c1d, ac1CD);
        ac2AB = fma2_(sp.x, c2d, ac2AB);  ac2CD = fma2_(sp.y, c2d, ac2CD);
        ac0AB = add2_(ac0AB, sp.x);       ac0CD = add2_(ac0CD, sp.y);
    }
    const ull TWO = dup_(2.0f), SCL = dup_(1.0f / 129.0f);
    float zp0s[4], zp1s[4], zp2s[4];
    {
        ull r;
        r = mul2_(fma2_(ac0AB, TWO, s0p.x), SCL); unpk_(r, zp0s[0], zp0s[1]);
        r = mul2_(fma2_(ac0CD, TWO, s0p.y), SCL); unpk_(r, zp0s[2], zp0s[3]);
        r = mul2_(fma2_(ac1AB, TWO, s0p.x), SCL); unpk_(r, zp1s[0], zp1s[1]);
        r = mul2_(fma2_(ac1CD, TWO, s0p.y), SCL); unpk_(r, zp1s[2], zp1s[3]);
        r = mul2_(fma2_(ac2AB, TWO, s0p.x), SCL); unpk_(r, zp2s[0], zp2s[1]);
        r = mul2_(fma2_(ac2CD, TWO, s0p.y), SCL); unpk_(r, zp2s[2], zp2s[3]);
    }

    // ---- per-frame: windowed IR build + 64x192 linear conv (dual-phase, even pairs only) ----
    #pragma unroll
    for (int ff = 0; ff < 4; ff++) {
        const int fi = ff * NWARP + w;

        // wb[128 +/- t] = win * zp (zp even-symmetric)
        wst_(wb, 128 + t1, __ldg(&g_win[64 + t1]) * zp1s[ff]);
        wst_(wb, 128 - t1, __ldg(&g_win[64 - t1]) * zp1s[ff]);
        wst_(wb, 128 + t2, __ldg(&g_win[64 + t2]) * zp2s[ff]);
        wst_(wb, 128 - t2, __ldg(&g_win[64 - t2]) * zp2s[ff]);
        if (l == 0) wst_(wb, 128, __ldg(&g_win[64]) * zp0s[ff]);
        __syncwarp();

        // lane ll owns outputs t = 8ll..8ll+7 (ll<24); lane 24 = boundary producer.
        // even taus -> accA_c = (E[8ll+2c], E[8ll+2c+1]); pairs at even alignment
        // odd  taus -> accB_c = (O[8ll+2c-1], O[8ll+2c]); pairs also even-aligned
        const float* xs = outb + fi * 192;
        const int ll = (l < 25) ? l : 0;
        ull a0 = 0, a1 = 0, a2 = 0, a3 = 0;
        ull b0 = 0, b1 = 0, b2 = 0, b3 = 0;
        ull v0, v1, v2, v3, v4, v5;   // pairs (B-2 .. B+3), B = 32+4*ll-2g
        {
            const ULL2 pa = wld_(wb, 15 + 2 * ll);
            const ULL2 pb = wld_(wb, 16 + 2 * ll);
            const ULL2 pc = wld_(wb, 17 + 2 * ll);
            v0 = pa.x; v1 = pa.y; v2 = pb.x; v3 = pb.y; v4 = pc.x; v5 = pc.y;
        }
        #pragma unroll
        for (int g = 0; g < 16; g++) {
            const float4 xq = *(const float4*)(xs + 4 * g);
            const ull x0 = dup_(xq.x), x1 = dup_(xq.y), x2 = dup_(xq.z), x3 = dup_(xq.w);
            a0 = fma2_(x0, v2, a0); a1 = fma2_(x0, v3, a1);
            a2 = fma2_(x0, v4, a2); a3 = fma2_(x0, v5, a3);
            b0 = fma2_(x1, v1, b0); b1 = fma2_(x1, v2, b1);
            b2 = fma2_(x1, v3, b2); b3 = fma2_(x1, v4, b3);
            a0 = fma2_(x2, v1, a0); a1 = fma2_(x2, v2, a1);
            a2 = fma2_(x2, v3, a2); a3 = fma2_(x2, v4, a3);
            b0 = fma2_(x3, v0, b0); b1 = fma2_(x3, v1, b1);
            b2 = fma2_(x3, v2, b2); b3 = fma2_(x3, v3, b3);
            if (g < 15) {
                const ULL2 nw = wld_(wb, 14 + 2 * ll - g);
                v5 = v3; v4 = v2; v3 = v1; v2 = v0;
                v1 = nw.y; v0 = nw.x;
            }
        }
        // combine phases; one cross-lane boundary term via shfl
        float aL0, aH0, aL1, aH1, aL2, aH2, aL3, aH3;
        float bL0, bH0, bL1, bH1, bL2, bH2, bL3, bH3;
        unpk_(a0, aL0, aH0); unpk_(a1, aL1, aH1);
        unpk_(a2, aL2, aH2); unpk_(a3, aL3, aH3);
        unpk_(b0, bL0, bH0); unpk_(b1, bL1, bH1);
        unpk_(b2, bL2, bH2); unpk_(b3, bL3, bH3);
        const float up = __shfl_down_sync(0xffffffffu, bL0, 1);
        __syncwarp();   // all lanes' x reads done before the row is overwritten
        if (l < 24) {
            float4 o03, o47;
            o03.x = aL0 + bH0; o03.y = aH0 + bL1;
            o03.z = aL1 + bH1; o03.w = aH1 + bL2;
            o47.x = aL2 + bH2; o47.y = aH2 + bL3;
            o47.z = aL3 + bH3; o47.w = aH3 + up;
            float4* op = (float4*)(outb + fi * 192 + 8 * l);
            op[0] = o03;
            op[1] = o47;
        }
        __syncwarp();   // wb/row settled before next frame
    }

    __syncthreads();

    // ---- overlap-add: interior exclusively owned, boundaries via atomics ----
    const size_t rowb = (size_t)b * OUT_S;
    const int gb = f0 * FL_;
    for (int p = tid; p < ACCLEN; p += 256) {
        const int P = gb + p;
        if (P >= OUT_S) continue;
        const int fhi = p >> 6;
        const int t0  = p & 63;
        float v = 0.f;
        if (fhi < NFRB)                 v += outb[fhi * 192 + t0];
        if (fhi >= 1 && fhi - 1 < NFRB) v += outb[(fhi - 1) * 192 + t0 + 64];
        if (fhi >= 2 && fhi - 2 < NFRB) v += outb[(fhi - 2) * 192 + t0 + 128];
        if (p >= 128 && p < 2048) out[rowb + P] = v;
        else                      atomicAdd(&out[rowb + P], v);
    }
}

extern "C" void kernel_launch(void* const* d_in, const int* in_sizes, int n_in,
                              void* d_out, int out_size) {
    const float* coeff = (const float*)d_in[0];
    const float* noise = (const float*)d_in[1];
    float* out = (float*)d_out;

    cudaFuncSetAttribute(fn_main, cudaFuncAttributeMaxDynamicSharedMemorySize, SMEM_TOT);
    prep_k<<<1024, 256>>>((float4*)out);
    dim3 grid(128, B_);
    fn_main<<<grid, 256, SMEM_TOT>>>(coeff, noise, out);
}

// round 11
// speedup vs baseline: 1.4388x; 1.0075x over previous
#include <cuda_runtime.h>
#include <math.h>

typedef unsigned long long ull;
struct __align__(16) ULL2 { ull x, y; };

#define B_     64
#define F_     4097
#define FCL_   65
#define FL_    64
#define OUT_S  262144
#define NFRB   32          // frames per block
#define NWARP  8
#define ACCLEN 2176        // (NFRB-1)*64 + 192

// ---------------- packed f32x2 helpers ----------------
__device__ __forceinline__ ull fma2_(ull a, ull b, ull c) {
    ull d; asm("fma.rn.f32x2 %0,%1,%2,%3;" : "=l"(d) : "l"(a), "l"(b), "l"(c)); return d;
}
__device__ __forceinline__ ull add2_(ull a, ull b) {
    ull d; asm("add.rn.f32x2 %0,%1,%2;" : "=l"(d) : "l"(a), "l"(b)); return d;
}
__device__ __forceinline__ ull mul2_(ull a, ull b) {
    ull d; asm("mul.rn.f32x2 %0,%1,%2;" : "=l"(d) : "l"(a), "l"(b)); return d;
}
__device__ __forceinline__ ull dup_(float x) {
    ull d; unsigned r = __float_as_uint(x);
    asm("mov.b64 %0,{%1,%1};" : "=l"(d) : "r"(r)); return d;
}
__device__ __forceinline__ void unpk_(ull v, float& lo, float& hi) {
    unsigned a, b; asm("mov.b64 {%0,%1},%2;" : "=r"(a), "=r"(b) : "l"(v));
    lo = __uint_as_float(a); hi = __uint_as_float(b);
}

// ---------------- small precise tables ----------------
__device__ float4 g_rot[32];   // lane l: (cos th*(l+1), sin th*(l+1), cos th*(l+33), sin th*(l+33))
__device__ float  g_win[130];

// prep: build tables AND zero only the block-boundary strips of out
__global__ void prep_k(float4* __restrict__ out4) {
    const int i = blockIdx.x * blockDim.x + threadIdx.x;
    const float TH = 6.283185307179586477f / 129.0f;
    if (i < 32) {
        g_rot[i] = make_float4(cosf(TH * (float)(i + 1)),  sinf(TH * (float)(i + 1)),
                               cosf(TH * (float)(i + 33)), sinf(TH * (float)(i + 33)));
    }
    if (i < 130) g_win[i] = 0.5f - 0.5f * cosf(TH * (float)i);
    if (i < 64 * 128 * 32) {
        const int b  = i >> 12;
        const int r  = i & 4095;
        const int q  = r >> 5;
        const int j4 = r & 31;
        out4[b * 65536 + q * 512 + j4] = make_float4(0.f, 0.f, 0.f, 0.f);
    }
}

__device__ __forceinline__ float msig(float x) {
    float sg = 1.0f / (1.0f + __expf(-x));
    return 2.0f * __powf(sg, 2.302585092994046f) + 1e-7f;
}

// ---------------- wirb XOR swizzle (16B-chunk granularity) ----------------
__device__ __forceinline__ int swz_(int c) { return c ^ ((c >> 3) & 7); }
__device__ __forceinline__ ULL2 wld_(const float* wb, int c) {
    return *(const ULL2*)(wb + (swz_(c) << 2));
}
__device__ __forceinline__ void wst_(float* wb, int i, float v) {
    int c = i >> 2;
    wb[(swz_(c) << 2) | (i & 3)] = v;
}

// ---------------- dynamic smem layout (bytes) ----------------
#define SINTJ_OFF  0        // float[8][65][4] = 8320
#define WIR_OFF    8320     // float[8][256]   = 8192 (swizzled; zero outside IR span)
#define OUTB_OFF   16512    // float[32][192]  = 24576 (x in [0..64), zp spill in [128..192))
#define SMEM_TOT   41088    // 40.1 KB -> 5 CTAs/SM

__global__ __launch_bounds__(256, 5) void fn_main(
        const float* __restrict__ coeff,   // (B, F, 65)
        const float* __restrict__ noise,   // (B, F, 64)
        float* __restrict__ out)           // (B, 262144)
{
    extern __shared__ __align__(16) char smdyn[];
    float* sIntJ = (float*)(smdyn + SINTJ_OFF);   // [w][k][ff]
    float* wirb  = (float*)(smdyn + WIR_OFF);     // [w][256] swizzled
    float* outb  = (float*)(smdyn + OUTB_OFF);    // [fi][192]

    const int tid = threadIdx.x;
    const int w   = tid >> 5;
    const int l   = tid & 31;
    const int q   = blockIdx.x;          // 0..127 (frames 0..4095; frame 4096 never contributes)
    const int b   = blockIdx.y;
    const int f0  = q * NFRB;

    // ---- stage inputs, zero wir buffers ----
    for (int i = tid; i < NWARP * 256; i += 256) wirb[i] = 0.f;
    const size_t cbo = ((size_t)b * F_ + f0) * FCL_;
    for (int e = tid; e < NFRB * FCL_; e += 256) {
        int fi = e / 65, k = e - fi * 65;
        sIntJ[(((fi & 7) * 65) + k) * 4 + (fi >> 3)] = msig(coeff[cbo + e]);
    }
    // x staged plain into the first 64 floats of each outb row
    const size_t nbo = ((size_t)b * F_ + f0) * FL_;
    for (int e = tid; e < NFRB * FL_; e += 256) {
        int fi = e >> 6, t = e & 63;
        outb[fi * 192 + t] = 2.f * noise[nbo + e] - 1.f;
    }
    __syncthreads();

    const int t1 = l + 1, t2 = l + 33;
    float* wb = wirb + w * 256;

    // per-lane constants held in registers
    const float4 rt = __ldg(&g_rot[l]);          // (rc1, rs1, rc2, rs2)
    const float w1p = __ldg(&g_win[64 + t1]), w1m = __ldg(&g_win[64 - t1]);
    const float w2p = __ldg(&g_win[64 + t2]), w2m = __ldg(&g_win[64 - t2]);
    const float wc  = __ldg(&g_win[64]);

    // ---- cosine transform via rotation recurrence, 4 frames jointly (packed f32x2) ----
    // zp[t] = (s0 + 2*sum_{k=1..64} s_k cos(2pi k t/129)) / 129 ; lane handles t1, t2
    const float* sw = sIntJ + w * 65 * 4;
    ull ac0AB = 0, ac0CD = 0, ac1AB = 0, ac1CD = 0, ac2AB = 0, ac2CD = 0;
    const ULL2 s0p = *(const ULL2*)sw;
    {
        float c1 = rt.x, s1 = rt.y, c2 = rt.z, s2 = rt.w;   // state at k (seed = k=1)
        #pragma unroll 8
        for (int k = 1; k <= 64; k++) {
            const ULL2 sp = *(const ULL2*)(sw + k * 4);   // broadcast LDS.128
            const ull c1d = dup_(c1), c2d = dup_(c2);
            ac1AB = fma2_(sp.x, c1d, ac1AB);  ac1CD = fma2_(sp.y, c1d, ac1CD);
            ac2AB = fma2_(sp.x, c2d, ac2AB);  ac2CD = fma2_(sp.y, c2d, ac2CD);
            ac0AB = add2_(ac0AB, sp.x);       ac0CD = add2_(ac0CD, sp.y);
            const float nc1 = c1 * rt.x - s1 * rt.y;
            const float ns1 = s1 * rt.x + c1 * rt.y;
            c1 = nc1; s1 = ns1;
            const float nc2 = c2 * rt.z - s2 * rt.w;
            const float ns2 = s2 * rt.z + c2 * rt.w;
            c2 = nc2; s2 = ns2;
        }
    }
    const ull TWO = dup_(2.0f), SCL = dup_(1.0f / 129.0f);
    float zp0s[4];
    {
        // zp1/zp2 spill through each frame's own row tail (same-lane store/reload)
        float zA, zB;
        ull r;
        r = mul2_(fma2_(ac0AB, TWO, s0p.x), SCL); unpk_(r, zp0s[0], zp0s[1]);
        r = mul2_(fma2_(ac0CD, TWO, s0p.y), SCL); unpk_(r, zp0s[2], zp0s[3]);
        r = mul2_(fma2_(ac1AB, TWO, s0p.x), SCL); unpk_(r, zA, zB);
        outb[w * 192 + 128 + l] = zA;  outb[(8 + w) * 192 + 128 + l] = zB;
        r = mul2_(fma2_(ac1CD, TWO, s0p.y), SCL); unpk_(r, zA, zB);
        outb[(16 + w) * 192 + 128 + l] = zA;  outb[(24 + w) * 192 + 128 + l] = zB;
        r = mul2_(fma2_(ac2AB, TWO, s0p.x), SCL); unpk_(r, zA, zB);
        outb[w * 192 + 160 + l] = zA;  outb[(8 + w) * 192 + 160 + l] = zB;
        r = mul2_(fma2_(ac2CD, TWO, s0p.y), SCL); unpk_(r, zA, zB);
        outb[(16 + w) * 192 + 160 + l] = zA;  outb[(24 + w) * 192 + 160 + l] = zB;
    }

    // ---- per-frame: windowed IR build + 64x192 linear conv (dual-phase, even pairs) ----
    #pragma unroll
    for (int ff = 0; ff < 4; ff++) {
        const int fi = ff * NWARP + w;
        const float zp1 = outb[fi * 192 + 128 + l];   // same-lane reload
        const float zp2 = outb[fi * 192 + 160 + l];

        // wb[128 +/- t] = win * zp (zp even-symmetric)
        wst_(wb, 128 + t1, w1p * zp1);
        wst_(wb, 128 - t1, w1m * zp1);
        wst_(wb, 128 + t2, w2p * zp2);
        wst_(wb, 128 - t2, w2m * zp2);
        if (l == 0) wst_(wb, 128, wc * zp0s[ff]);
        __syncwarp();

        // lane ll owns outputs t = 8ll..8ll+7 (ll<24); lane 24 = boundary producer.
        const float* xs = outb + fi * 192;
        const int ll = (l < 25) ? l : 0;
        ull a0 = 0, a1 = 0, a2 = 0, a3 = 0;
        ull b0 = 0, b1 = 0, b2 = 0, b3 = 0;
        ull v0, v1, v2, v3, v4, v5;   // pairs (B-2 .. B+3), B = 32+4*ll-2g
        {
            const ULL2 pa = wld_(wb, 15 + 2 * ll);
            const ULL2 pb = wld_(wb, 16 + 2 * ll);
            const ULL2 pc = wld_(wb, 17 + 2 * ll);
            v0 = pa.x; v1 = pa.y; v2 = pb.x; v3 = pb.y; v4 = pc.x; v5 = pc.y;
        }
        #pragma unroll
        for (int g = 0; g < 16; g++) {
            const float4 xq = *(const float4*)(xs + 4 * g);
            const ull x0 = dup_(xq.x), x1 = dup_(xq.y), x2 = dup_(xq.z), x3 = dup_(xq.w);
            a0 = fma2_(x0, v2, a0); a1 = fma2_(x0, v3, a1);
            a2 = fma2_(x0, v4, a2); a3 = fma2_(x0, v5, a3);
            b0 = fma2_(x1, v1, b0); b1 = fma2_(x1, v2, b1);
            b2 = fma2_(x1, v3, b2); b3 = fma2_(x1, v4, b3);
            a0 = fma2_(x2, v1, a0); a1 = fma2_(x2, v2, a1);
            a2 = fma2_(x2, v3, a2); a3 = fma2_(x2, v4, a3);
            b0 = fma2_(x3, v0, b0); b1 = fma2_(x3, v1, b1);
            b2 = fma2_(x3, v2, b2); b3 = fma2_(x3, v3, b3);
            if (g < 15) {
                const ULL2 nw = wld_(wb, 14 + 2 * ll - g);
                v5 = v3; v4 = v2; v3 = v1; v2 = v0;
                v1 = nw.y; v0 = nw.x;
            }
        }
        // combine phases; one cross-lane boundary term via shfl
        float aL0, aH0, aL1, aH1, aL2, aH2, aL3, aH3;
        float bL0, bH0, bL1, bH1, bL2, bH2, bL3, bH3;
        unpk_(a0, aL0, aH0); unpk_(a1, aL1, aH1);
        unpk_(a2, aL2, aH2); unpk_(a3, aL3, aH3);
        unpk_(b0, bL0, bH0); unpk_(b1, bL1, bH1);
        unpk_(b2, bL2, bH2); unpk_(b3, bL3, bH3);
        const float up = __shfl_down_sync(0xffffffffu, bL0, 1);
        __syncwarp();   // all lanes' x reads done before the row is overwritten
        if (l < 24) {
            float4 o03, o47;
            o03.x = aL0 + bH0; o03.y = aH0 + bL1;
            o03.z = aL1 + bH1; o03.w = aH1 + bL2;
            o47.x = aL2 + bH2; o47.y = aH2 + bL3;
            o47.z = aL3 + bH3; o47.w = aH3 + up;
            float4* op = (float4*)(outb + fi * 192 + 8 * l);
            op[0] = o03;
            op[1] = o47;
        }
        __syncwarp();   // wb/row settled before next frame
    }

    __syncthreads();

    // ---- overlap-add: interior exclusively owned, boundaries via atomics ----
    const size_t rowb = (size_t)b * OUT_S;
    const int gb = f0 * FL_;
    for (int p = tid; p < ACCLEN; p += 256) {
        const int P = gb + p;
        if (P >= OUT_S) continue;
        const int fhi = p >> 6;
        const int t0  = p & 63;
        float v = 0.f;
        if (fhi < NFRB)                 v += outb[fhi * 192 + t0];
        if (fhi >= 1 && fhi - 1 < NFRB) v += outb[(fhi - 1) * 192 + t0 + 64];
        if (fhi >= 2 && fhi - 2 < NFRB) v += outb[(fhi - 2) * 192 + t0 + 128];
        if (p >= 128 && p < 2048) out[rowb + P] = v;
        else                      atomicAdd(&out[rowb + P], v);
    }
}

extern "C" void kernel_launch(void* const* d_in, const int* in_sizes, int n_in,
                              void* d_out, int out_size) {
    const float* coeff = (const float*)d_in[0];
    const float* noise = (const float*)d_in[1];
    float* out = (float*)d_out;

    cudaFuncSetAttribute(fn_main, cudaFuncAttributeMaxDynamicSharedMemorySize, SMEM_TOT);
    prep_k<<<1024, 256>>>((float4*)out);
    dim3 grid(128, B_);
    fn_main<<<grid, 256, SMEM_TOT>>>(coeff, noise, out);
}